// round 5
// baseline (speedup 1.0000x reference)
#include <cuda_runtime.h>
#include <math.h>

#define Bb 2
#define Hh 48
#define Ww 48
#define Cc 192
#define NH 8
#define Nn 2304            // Hh*Ww
#define QW 2               // queries per warp
#define NWARPS 32          // 1024 threads
#define QT (QW*NWARPS)     // 64 queries per block
#define NTILES (Nn/QT)     // 36
// SCALE * log2(e): fold softmax scale and exp->ex2 conversion into q & bias
#define SL2E 0.5100420914154871f

// smem: skA,skB,svA,svB: 4 * 2304 * 16B = 147456
//       sph, spw: 2 * 32 warps * 48 pos * 8B = 24576
#define SMEM_BYTES (Nn*4*16 + 2*NWARPS*48*8)

typedef unsigned long long ull;

__device__ __forceinline__ ull pk2(float lo, float hi) {
    ull r; asm("mov.b64 %0,{%1,%2};" : "=l"(r) : "f"(lo), "f"(hi)); return r;
}
__device__ __forceinline__ void upk2(ull v, float& lo, float& hi) {
    asm("mov.b64 {%0,%1},%2;" : "=f"(lo), "=f"(hi) : "l"(v));
}
__device__ __forceinline__ ull fma2(ull a, ull b, ull c) {
    ull d; asm("fma.rn.f32x2 %0,%1,%2,%3;" : "=l"(d) : "l"(a), "l"(b), "l"(c)); return d;
}
__device__ __forceinline__ ull add2(ull a, ull b) {
    ull d; asm("add.rn.f32x2 %0,%1,%2;" : "=l"(d) : "l"(a), "l"(b)); return d;
}
__device__ __forceinline__ ull mul2(ull a, ull b) {
    ull d; asm("mul.rn.f32x2 %0,%1,%2;" : "=l"(d) : "l"(a), "l"(b)); return d;
}
__device__ __forceinline__ float ex2f(float x) {
    float r; asm("ex2.approx.f32 %0,%1;" : "=f"(r) : "f"(x)); return r;
}

__global__ __launch_bounds__(1024, 1)
void attn_aug2d_kernel(const float* __restrict__ inp,
                       const float* __restrict__ relw,
                       const float* __restrict__ relh,
                       float* __restrict__ out)
{
    extern __shared__ float smem[];
    ulonglong2* skA = (ulonglong2*)smem;   // [Nn] k dims 0..3
    ulonglong2* skB = skA + Nn;            // [Nn] k dims 4..7
    ulonglong2* svA = skB + Nn;            // [Nn] v dims 0..3
    ulonglong2* svB = svA + Nn;            // [Nn] v dims 4..7
    ull* sph = (ull*)(svB + Nn);           // [NWARPS][48] (2 floats = 8B each)
    ull* spw = sph + NWARPS*48;            // [NWARPS][48]

    const int tid  = threadIdx.x;
    const int warp = tid >> 5;
    const int lane = tid & 31;
    const int tile = blockIdx.x;
    const int h    = blockIdx.y;
    const int b    = blockIdx.z;

    // ---- stage K, V into smem ----
    for (int m = tid; m < Nn; m += 1024) {
        const float* base = inp + ((size_t)(b*Nn + m))*Cc + 64 + h*8; // k channels
        skA[m] = *(const ulonglong2*)(base);
        skB[m] = *(const ulonglong2*)(base + 4);
        svA[m] = *(const ulonglong2*)(base + 64);  // v = k + 64 channels
        svB[m] = *(const ulonglong2*)(base + 68);
    }

    // ---- per-warp separable bias tables (pre-scaled by SCALE*log2e) ----
    // sph[warp][X] = 2 floats: (q_qi . rel_h[X - x_qi + 47]) * SL2E
    // spw[warp][Y] = 2 floats: (q_qi . rel_w[Y - y_qi + 47]) * SL2E
    const int q0 = tile*QT + warp*QW;
    for (int e = lane; e < 2*48*QW; e += 32) {
        int t   = e / (48*QW);         // 0 = ph, 1 = pw
        int rem = e - t*(48*QW);
        int pos = rem >> 1;
        int qi  = rem & 1;
        int n   = q0 + qi;
        int x   = n / 48;
        int y   = n - x*48;
        const float* qptr = inp + ((size_t)(b*Nn + n))*Cc + h*8;
        const float* rel  = (t == 0) ? (relh + (pos - x + 47)*8)
                                     : (relw + (pos - y + 47)*8);
        float s = 0.f;
        #pragma unroll
        for (int d = 0; d < 8; d++) s += qptr[d]*rel[d];
        float* dst = (float*)((t == 0) ? sph : spw);
        dst[(warp*48 + pos)*2 + qi] = s * SL2E;
    }
    __syncthreads();

    // ---- queries packed over dims: qXp[p] = (q_2p, q_2p+1) * SL2E ----
    ull q0p[4], q1p[4];
    {
        const ull sl2 = pk2(SL2E, SL2E);
        #pragma unroll
        for (int i = 0; i < QW; i++) {
            const float* qptr = inp + ((size_t)(b*Nn + q0 + i))*Cc + h*8;
            ulonglong2 a = *(const ulonglong2*)(qptr);
            ulonglong2 c = *(const ulonglong2*)(qptr + 4);
            ull* dst = (i==0) ? q0p : q1p;
            dst[0] = mul2(a.x, sl2);
            dst[1] = mul2(a.y, sl2);
            dst[2] = mul2(c.x, sl2);
            dst[3] = mul2(c.y, sl2);
        }
    }

    ull acc0[4], acc1[4];
    #pragma unroll
    for (int p = 0; p < 4; p++) { acc0[p]=0; acc1[p]=0; }
    float s0=0.f, s1=0.f;

    const ull* php = sph + warp*48;        // ph[X], X starts at 0 (lane < 48)
    const ull* pww = spw + warp*48;
    int m = lane;
    int r = lane;                          // r = Y = key - 48*X

    #pragma unroll 3
    for (int it = 0; it < Nn/32; it++) {
        ulonglong2 kA = skA[m], kB = skB[m];
        ulonglong2 vA = svA[m], vB = svB[m];
        ull ph = *php;
        ull pw = pww[r];

        ull pp01 = add2(ph, pw);

        ull d0 = mul2(q0p[0], kA.x);
        ull d1 = mul2(q1p[0], kA.x);
        d0 = fma2(q0p[1], kA.y, d0); d1 = fma2(q1p[1], kA.y, d1);
        d0 = fma2(q0p[2], kB.x, d0); d1 = fma2(q1p[2], kB.x, d1);
        d0 = fma2(q0p[3], kB.y, d0); d1 = fma2(q1p[3], kB.y, d1);

        float b0,b1, lo,hi;
        upk2(pp01, b0, b1);
        upk2(d0, lo, hi); float w0 = ex2f(lo + hi + b0);
        upk2(d1, lo, hi); float w1 = ex2f(lo + hi + b1);

        s0 += w0; s1 += w1;

        ull wd;
        wd = pk2(w0,w0);
        acc0[0]=fma2(wd,vA.x,acc0[0]); acc0[1]=fma2(wd,vA.y,acc0[1]);
        acc0[2]=fma2(wd,vB.x,acc0[2]); acc0[3]=fma2(wd,vB.y,acc0[3]);
        wd = pk2(w1,w1);
        acc1[0]=fma2(wd,vA.x,acc1[0]); acc1[1]=fma2(wd,vA.y,acc1[1]);
        acc1[2]=fma2(wd,vB.x,acc1[2]); acc1[3]=fma2(wd,vB.y,acc1[3]);

        m += 32;
        r += 32;
        if (r >= 48) { r -= 48; php++; }
    }

    // ---- warp reduction (packed accs + scalar sums) ----
    #pragma unroll
    for (int o = 16; o > 0; o >>= 1) {
        s0 += __shfl_xor_sync(0xffffffffu, s0, o);
        s1 += __shfl_xor_sync(0xffffffffu, s1, o);
        #pragma unroll
        for (int p = 0; p < 4; p++) {
            acc0[p] = add2(acc0[p], __shfl_xor_sync(0xffffffffu, acc0[p], o));
            acc1[p] = add2(acc1[p], __shfl_xor_sync(0xffffffffu, acc1[p], o));
        }
    }

    if (lane == 0) {
        float r0 = 1.0f/s0, r1 = 1.0f/s1;
        ull rd;
        ulonglong2 oA, oB;
        size_t obase = ((size_t)(b*Nn + q0))*64 + h*8;

        rd = pk2(r0,r0);
        oA.x = mul2(acc0[0],rd); oA.y = mul2(acc0[1],rd);
        oB.x = mul2(acc0[2],rd); oB.y = mul2(acc0[3],rd);
        *(ulonglong2*)(out + obase)      = oA;
        *(ulonglong2*)(out + obase + 4)  = oB;

        rd = pk2(r1,r1);
        oA.x = mul2(acc1[0],rd); oA.y = mul2(acc1[1],rd);
        oB.x = mul2(acc1[2],rd); oB.y = mul2(acc1[3],rd);
        *(ulonglong2*)(out + obase + 64)     = oA;
        *(ulonglong2*)(out + obase + 64 + 4) = oB;
    }
}

extern "C" void kernel_launch(void* const* d_in, const int* in_sizes, int n_in,
                              void* d_out, int out_size)
{
    const float* inp  = (const float*)d_in[0];
    const float* relw = (const float*)d_in[1];
    const float* relh = (const float*)d_in[2];
    float* out = (float*)d_out;

    cudaFuncSetAttribute(attn_aug2d_kernel,
                         cudaFuncAttributeMaxDynamicSharedMemorySize, SMEM_BYTES);
    dim3 grid(NTILES, NH, Bb);
    attn_aug2d_kernel<<<grid, 1024, SMEM_BYTES>>>(inp, relw, relh, out);
}

// round 6
// speedup vs baseline: 1.0036x; 1.0036x over previous
#include <cuda_runtime.h>
#include <math.h>

#define Bb 2
#define Hh 48
#define Ww 48
#define Cc 192
#define NH 8
#define Nn 2304            // Hh*Ww
#define QW 2               // queries per warp
#define NWARPS 32          // 1024 threads
#define QT (QW*NWARPS)     // 64 queries per block
#define NTILES (Nn/QT)     // 36
// SCALE * log2(e): fold softmax scale and exp->ex2 conversion into q & bias
#define SL2E 0.5100420914154871f

// smem: skA,skB,svA,svB: 4 * 2304 * 16B = 147456
//       sph, spw: 2 * 32 warps * 48 pos * 8B = 24576
#define SMEM_BYTES (Nn*4*16 + 2*NWARPS*48*8)

typedef unsigned long long ull;

__device__ __forceinline__ ull pk2(float lo, float hi) {
    ull r; asm("mov.b64 %0,{%1,%2};" : "=l"(r) : "f"(lo), "f"(hi)); return r;
}
__device__ __forceinline__ void upk2(ull v, float& lo, float& hi) {
    asm("mov.b64 {%0,%1},%2;" : "=f"(lo), "=f"(hi) : "l"(v));
}
__device__ __forceinline__ ull fma2(ull a, ull b, ull c) {
    ull d; asm("fma.rn.f32x2 %0,%1,%2,%3;" : "=l"(d) : "l"(a), "l"(b), "l"(c)); return d;
}
__device__ __forceinline__ ull add2(ull a, ull b) {
    ull d; asm("add.rn.f32x2 %0,%1,%2;" : "=l"(d) : "l"(a), "l"(b)); return d;
}
__device__ __forceinline__ ull mul2(ull a, ull b) {
    ull d; asm("mul.rn.f32x2 %0,%1,%2;" : "=l"(d) : "l"(a), "l"(b)); return d;
}
__device__ __forceinline__ float ex2f(float x) {
    float r; asm("ex2.approx.f32 %0,%1;" : "=f"(r) : "f"(x)); return r;
}

__global__ __launch_bounds__(1024, 1)
void attn_aug2d_kernel(const float* __restrict__ inp,
                       const float* __restrict__ relw,
                       const float* __restrict__ relh,
                       float* __restrict__ out)
{
    extern __shared__ float smem[];
    ulonglong2* skA = (ulonglong2*)smem;   // [Nn] k dims 0..3
    ulonglong2* skB = skA + Nn;            // [Nn] k dims 4..7
    ulonglong2* svA = skB + Nn;            // [Nn] v dims 0..3
    ulonglong2* svB = svA + Nn;            // [Nn] v dims 4..7
    ull* sph = (ull*)(svB + Nn);           // [NWARPS][48] (2 floats = 8B each)
    ull* spw = sph + NWARPS*48;            // [NWARPS][48]

    const int tid  = threadIdx.x;
    const int warp = tid >> 5;
    const int lane = tid & 31;
    const int tile = blockIdx.x;
    const int h    = blockIdx.y;
    const int b    = blockIdx.z;

    // ---- stage K, V into smem ----
    for (int m = tid; m < Nn; m += 1024) {
        const float* base = inp + ((size_t)(b*Nn + m))*Cc + 64 + h*8; // k channels
        skA[m] = *(const ulonglong2*)(base);
        skB[m] = *(const ulonglong2*)(base + 4);
        svA[m] = *(const ulonglong2*)(base + 64);  // v = k + 64 channels
        svB[m] = *(const ulonglong2*)(base + 68);
    }

    // ---- per-warp separable bias tables (pre-scaled by SCALE*log2e) ----
    // sph[warp][X] = 2 floats: (q_qi . rel_h[X - x_qi + 47]) * SL2E
    // spw[warp][Y] = 2 floats: (q_qi . rel_w[Y - y_qi + 47]) * SL2E
    const int q0 = tile*QT + warp*QW;
    for (int e = lane; e < 2*48*QW; e += 32) {
        int t   = e / (48*QW);         // 0 = ph, 1 = pw
        int rem = e - t*(48*QW);
        int pos = rem >> 1;
        int qi  = rem & 1;
        int n   = q0 + qi;
        int x   = n / 48;
        int y   = n - x*48;
        const float* qptr = inp + ((size_t)(b*Nn + n))*Cc + h*8;
        const float* rel  = (t == 0) ? (relh + (pos - x + 47)*8)
                                     : (relw + (pos - y + 47)*8);
        float s = 0.f;
        #pragma unroll
        for (int d = 0; d < 8; d++) s += qptr[d]*rel[d];
        float* dst = (float*)((t == 0) ? sph : spw);
        dst[(warp*48 + pos)*2 + qi] = s * SL2E;
    }
    __syncthreads();

    // ---- queries packed over dims: qXp[p] = (q_2p, q_2p+1) * SL2E ----
    ull q0p[4], q1p[4];
    {
        const ull sl2 = pk2(SL2E, SL2E);
        #pragma unroll
        for (int i = 0; i < QW; i++) {
            const float* qptr = inp + ((size_t)(b*Nn + q0 + i))*Cc + h*8;
            ulonglong2 a = *(const ulonglong2*)(qptr);
            ulonglong2 c = *(const ulonglong2*)(qptr + 4);
            ull* dst = (i==0) ? q0p : q1p;
            dst[0] = mul2(a.x, sl2);
            dst[1] = mul2(a.y, sl2);
            dst[2] = mul2(c.x, sl2);
            dst[3] = mul2(c.y, sl2);
        }
    }

    ull acc0[4], acc1[4];
    #pragma unroll
    for (int p = 0; p < 4; p++) { acc0[p]=0; acc1[p]=0; }
    float s0=0.f, s1=0.f;

    const ull* php = sph + warp*48;        // ph[X], X starts at 0 (lane < 48)
    const ull* pww = spw + warp*48;
    int m = lane;
    int r = lane;                          // r = Y = key - 48*X

    #pragma unroll 3
    for (int it = 0; it < Nn/32; it++) {
        ulonglong2 kA = skA[m], kB = skB[m];
        ulonglong2 vA = svA[m], vB = svB[m];
        ull ph = *php;
        ull pw = pww[r];

        ull pp01 = add2(ph, pw);

        ull d0 = mul2(q0p[0], kA.x);
        ull d1 = mul2(q1p[0], kA.x);
        d0 = fma2(q0p[1], kA.y, d0); d1 = fma2(q1p[1], kA.y, d1);
        d0 = fma2(q0p[2], kB.x, d0); d1 = fma2(q1p[2], kB.x, d1);
        d0 = fma2(q0p[3], kB.y, d0); d1 = fma2(q1p[3], kB.y, d1);

        float b0,b1, lo,hi;
        upk2(pp01, b0, b1);
        upk2(d0, lo, hi); float w0 = ex2f(lo + hi + b0);
        upk2(d1, lo, hi); float w1 = ex2f(lo + hi + b1);

        s0 += w0; s1 += w1;

        ull wd;
        wd = pk2(w0,w0);
        acc0[0]=fma2(wd,vA.x,acc0[0]); acc0[1]=fma2(wd,vA.y,acc0[1]);
        acc0[2]=fma2(wd,vB.x,acc0[2]); acc0[3]=fma2(wd,vB.y,acc0[3]);
        wd = pk2(w1,w1);
        acc1[0]=fma2(wd,vA.x,acc1[0]); acc1[1]=fma2(wd,vA.y,acc1[1]);
        acc1[2]=fma2(wd,vB.x,acc1[2]); acc1[3]=fma2(wd,vB.y,acc1[3]);

        m += 32;
        r += 32;
        if (r >= 48) { r -= 48; php++; }
    }

    // ---- warp reduction (packed accs + scalar sums) ----
    #pragma unroll
    for (int o = 16; o > 0; o >>= 1) {
        s0 += __shfl_xor_sync(0xffffffffu, s0, o);
        s1 += __shfl_xor_sync(0xffffffffu, s1, o);
        #pragma unroll
        for (int p = 0; p < 4; p++) {
            acc0[p] = add2(acc0[p], __shfl_xor_sync(0xffffffffu, acc0[p], o));
            acc1[p] = add2(acc1[p], __shfl_xor_sync(0xffffffffu, acc1[p], o));
        }
    }

    if (lane == 0) {
        float r0 = 1.0f/s0, r1 = 1.0f/s1;
        ull rd;
        ulonglong2 oA, oB;
        size_t obase = ((size_t)(b*Nn + q0))*64 + h*8;

        rd = pk2(r0,r0);
        oA.x = mul2(acc0[0],rd); oA.y = mul2(acc0[1],rd);
        oB.x = mul2(acc0[2],rd); oB.y = mul2(acc0[3],rd);
        *(ulonglong2*)(out + obase)      = oA;
        *(ulonglong2*)(out + obase + 4)  = oB;

        rd = pk2(r1,r1);
        oA.x = mul2(acc1[0],rd); oA.y = mul2(acc1[1],rd);
        oB.x = mul2(acc1[2],rd); oB.y = mul2(acc1[3],rd);
        *(ulonglong2*)(out + obase + 64)     = oA;
        *(ulonglong2*)(out + obase + 64 + 4) = oB;
    }
}

extern "C" void kernel_launch(void* const* d_in, const int* in_sizes, int n_in,
                              void* d_out, int out_size)
{
    const float* inp  = (const float*)d_in[0];
    const float* relw = (const float*)d_in[1];
    const float* relh = (const float*)d_in[2];
    float* out = (float*)d_out;

    cudaFuncSetAttribute(attn_aug2d_kernel,
                         cudaFuncAttributeMaxDynamicSharedMemorySize, SMEM_BYTES);
    dim3 grid(NTILES, NH, Bb);
    attn_aug2d_kernel<<<grid, 1024, SMEM_BYTES>>>(inp, relw, relh, out);
}

// round 8
// speedup vs baseline: 1.2125x; 1.2081x over previous
#include <cuda_runtime.h>
#include <cstdint>

#define Nn 2304
#define Cc 192
#define QTQ 128        // queries per CTA
#define NTILES 24      // key tiles of 96
#define SL2E 0.5100420914154871f

// smem word offsets
#define W_KT   0                    // KT [8][104]
#define W_VT   (8*104)              // VT [8][104]
#define W_PH   (2*8*104)            // phT [128][49]
#define W_PW   (W_PH + 128*49)      // pwT [128][50]
#define W_OS   (W_PW + 128*50)      // O partials [2][128][8]
#define W_SS   (W_OS + 2*128*8)     // sums [2][128]
#define SMEM_BYTES ((W_SS + 256)*4)

__device__ __forceinline__ float ex2f(float x){
    float r; asm("ex2.approx.f32 %0,%1;" : "=f"(r) : "f"(x)); return r;
}
__device__ __forceinline__ float tf32r(float x){
    uint32_t r; asm("cvt.rna.tf32.f32 %0,%1;" : "=r"(r) : "f"(x));
    return __uint_as_float(r);
}
__device__ __forceinline__ void mma16n8k8(
    float& d0, float& d1, float& d2, float& d3,
    uint32_t a0, uint32_t a1, uint32_t a2, uint32_t a3,
    uint32_t b0, uint32_t b1,
    float c0, float c1, float c2, float c3)
{
    asm volatile(
        "mma.sync.aligned.m16n8k8.row.col.f32.tf32.tf32.f32 "
        "{%0,%1,%2,%3},{%4,%5,%6,%7},{%8,%9},{%10,%11,%12,%13};"
        : "=f"(d0),"=f"(d1),"=f"(d2),"=f"(d3)
        : "r"(a0),"r"(a1),"r"(a2),"r"(a3),"r"(b0),"r"(b1),
          "f"(c0),"f"(c1),"f"(c2),"f"(c3));
}

__global__ __launch_bounds__(512, 1)
void attn_aug2d_mma(const float* __restrict__ inp,
                    const float* __restrict__ relw,
                    const float* __restrict__ relh,
                    float* __restrict__ out)
{
    extern __shared__ float sm[];
    const int tid  = threadIdx.x;
    const int warp = tid >> 5;
    const int lane = tid & 31;
    const int g    = lane >> 2;       // group id (rows)
    const int t    = lane & 3;        // thread in group
    const int strip = warp >> 3;      // 0/1: which 48-key half of the 96-tile
    const int mrow  = (warp & 7) << 4;// 16-query row block
    const int h = blockIdx.y, b = blockIdx.z;
    const int qbase = blockIdx.x * QTQ;

    // ---- bias tables: phT[q][X] (stride 49), pwT[q][Y] (stride 50), scaled SL2E ----
    for (int e = tid; e < 2*128*48; e += 512){
        int t0  = (e >= 6144);
        int rem = e - t0*6144;
        int q   = rem / 48;
        int pos = rem - q*48;
        int n   = qbase + q;
        int x   = n / 48, y = n - x*48;
        const float* qp  = inp + ((size_t)(b*Nn + n))*Cc + h*8;
        const float* rel = t0 ? (relw + (pos - y + 47)*8) : (relh + (pos - x + 47)*8);
        float s = 0.f;
        #pragma unroll
        for (int d = 0; d < 8; d++) s += qp[d]*rel[d];
        sm[(t0 ? (W_PW + q*50) : (W_PH + q*49)) + pos] = s * SL2E;
    }

    // ---- Q fragment (A of GEMM1), tf32-rounded, pre-scaled ----
    const int qa = mrow + g, qb = qa + 8;
    const float* qpa = inp + ((size_t)(b*Nn + qbase + qa))*Cc + h*8;
    const float* qpb = inp + ((size_t)(b*Nn + qbase + qb))*Cc + h*8;
    const uint32_t aq0 = __float_as_uint(tf32r(qpa[t]   * SL2E));
    const uint32_t aq1 = __float_as_uint(tf32r(qpb[t]   * SL2E));
    const uint32_t aq2 = __float_as_uint(tf32r(qpa[t+4] * SL2E));
    const uint32_t aq3 = __float_as_uint(tf32r(qpb[t+4] * SL2E));

    float o0=0.f, o1=0.f, o2=0.f, o3=0.f;   // O[16q x 8d] fragment (strip-partial)
    float sum0=0.f, sum1=0.f;
    const int idx0 = (lane & ~3) | (t >> 1);
    const int idx1 = idx0 + 2;
    const bool hi  = (t & 1);
    const int kb   = strip * 48;            // strip base within 96-key tile

    for (int tile = 0; tile < NTILES; tile++){
        __syncthreads();   // prior tile's K/V reads done
        // ---- stage KT[d][key], VT[d][key] (tf32-rounded) ----
        for (int i = tid; i < 768; i += 512){
            int key = i >> 3, d = i & 7;
            const float* p = inp + ((size_t)(b*Nn + tile*96 + key))*Cc + h*8;
            sm[W_KT + d*104 + key] = tf32r(p[64  + d]);
            sm[W_VT + d*104 + key] = tf32r(p[128 + d]);
        }
        __syncthreads();

        const int X = 2*tile + strip;
        const float pha = sm[W_PH + qa*49 + X];
        const float phb = sm[W_PH + qb*49 + X];

        #pragma unroll
        for (int j = 0; j < 6; j++){
            const int kj = kb + 8*j;
            // GEMM1 B-frag: K^T
            uint32_t kb0 = __float_as_uint(sm[W_KT + t*104     + kj + g]);
            uint32_t kb1 = __float_as_uint(sm[W_KT + (t+4)*104 + kj + g]);
            float s0, s1, s2, s3;
            mma16n8k8(s0,s1,s2,s3, aq0,aq1,aq2,aq3, kb0,kb1, 0.f,0.f,0.f,0.f);

            // bias + exp (pw: Y = strip-local key index = 8j+2t, aligned pair)
            float2 pwa = *(const float2*)&sm[W_PW + qa*50 + 8*j + 2*t];
            float2 pwb = *(const float2*)&sm[W_PW + qb*50 + 8*j + 2*t];
            float w0f = tf32r(ex2f(s0 + pha + pwa.x));
            float w1f = tf32r(ex2f(s1 + pha + pwa.y));
            float w2f = tf32r(ex2f(s2 + phb + pwb.x));
            float w3f = tf32r(ex2f(s3 + phb + pwb.y));
            sum0 += w0f + w1f;
            sum1 += w2f + w3f;

            // C-frag -> A-frag transform (in-register shuffle)
            uint32_t w0 = __float_as_uint(w0f), w1 = __float_as_uint(w1f);
            uint32_t w2 = __float_as_uint(w2f), w3 = __float_as_uint(w3f);
            uint32_t u0, u1;
            u0 = __shfl_sync(0xffffffffu, w0, idx0);
            u1 = __shfl_sync(0xffffffffu, w1, idx0);
            uint32_t a0 = hi ? u1 : u0;
            u0 = __shfl_sync(0xffffffffu, w0, idx1);
            u1 = __shfl_sync(0xffffffffu, w1, idx1);
            uint32_t a2 = hi ? u1 : u0;
            u0 = __shfl_sync(0xffffffffu, w2, idx0);
            u1 = __shfl_sync(0xffffffffu, w3, idx0);
            uint32_t a1 = hi ? u1 : u0;
            u0 = __shfl_sync(0xffffffffu, w2, idx1);
            u1 = __shfl_sync(0xffffffffu, w3, idx1);
            uint32_t a3 = hi ? u1 : u0;

            // GEMM2 B-frag: V (VT[dim][key])
            uint32_t vb0 = __float_as_uint(sm[W_VT + g*104 + kj + t]);
            uint32_t vb1 = __float_as_uint(sm[W_VT + g*104 + kj + t + 4]);
            mma16n8k8(o0,o1,o2,o3, a0,a1,a2,a3, vb0,vb1, o0,o1,o2,o3);
        }
    }

    // ---- reduce sums within t-group (4 lanes share a row) ----
    sum0 += __shfl_xor_sync(0xffffffffu, sum0, 1);
    sum0 += __shfl_xor_sync(0xffffffffu, sum0, 2);
    sum1 += __shfl_xor_sync(0xffffffffu, sum1, 1);
    sum1 += __shfl_xor_sync(0xffffffffu, sum1, 2);
    if (t == 0){
        sm[W_SS + strip*128 + qa] = sum0;
        sm[W_SS + strip*128 + qb] = sum1;
    }
    // ---- O partials to smem ----
    *(float2*)&sm[W_OS + strip*1024 + qa*8 + 2*t] = make_float2(o0, o1);
    *(float2*)&sm[W_OS + strip*1024 + qb*8 + 2*t] = make_float2(o2, o3);
    __syncthreads();

    // ---- combine strips, normalize, write ----
    if (tid < 128){
        int q = tid;
        float r = 1.0f / (sm[W_SS + q] + sm[W_SS + 128 + q]);
        float4 A0 = *(float4*)&sm[W_OS + q*8];
        float4 A1 = *(float4*)&sm[W_OS + q*8 + 4];
        float4 B0 = *(float4*)&sm[W_OS + 1024 + q*8];
        float4 B1 = *(float4*)&sm[W_OS + 1024 + q*8 + 4];
        float* op = out + ((size_t)(b*Nn + qbase + q))*64 + h*8;
        ((float4*)op)[0] = make_float4((A0.x+B0.x)*r, (A0.y+B0.y)*r,
                                       (A0.z+B0.z)*r, (A0.w+B0.w)*r);
        ((float4*)op)[1] = make_float4((A1.x+B1.x)*r, (A1.y+B1.y)*r,
                                       (A1.z+B1.z)*r, (A1.w+B1.w)*r);
    }
}

extern "C" void kernel_launch(void* const* d_in, const int* in_sizes, int n_in,
                              void* d_out, int out_size)
{
    const float* inp  = (const float*)d_in[0];
    const float* relw = (const float*)d_in[1];
    const float* relh = (const float*)d_in[2];
    float* out = (float*)d_out;

    cudaFuncSetAttribute(attn_aug2d_mma,
                         cudaFuncAttributeMaxDynamicSharedMemorySize, SMEM_BYTES);
    dim3 grid(Nn/QTQ, 8, 2);
    attn_aug2d_mma<<<grid, 512, SMEM_BYTES>>>(inp, relw, relh, out);
}

// round 9
// speedup vs baseline: 1.4338x; 1.1825x over previous
#include <cuda_runtime.h>
#include <cstdint>

#define Nn 2304
#define Cc 192
#define QTQ 128        // queries per CTA
#define KTILE 144      // keys per tile (3 X-rows)
#define NTILES 16
#define KROW 2312      // KT/VT row stride (2304 + 8 pad: conflict-free frags)
#define SL2E 0.5100420914154871f

// smem float offsets
#define W_KT   0
#define W_VT   (8*KROW)              // 18496
#define W_PH   (2*8*KROW)            // 36992 : phT[128][49]
#define W_PW   (W_PH + 128*49)       // pwT[128][50]
#define W_OS   (W_PW + 128*50)       // O partials [3][128][8]
#define W_SS   (W_OS + 3*128*8)      // sums [3][128]
#define SMEM_BYTES ((W_SS + 3*128)*4)   // 212480 B

__device__ __forceinline__ float ex2f(float x){
    float r; asm("ex2.approx.f32 %0,%1;" : "=f"(r) : "f"(x)); return r;
}
__device__ __forceinline__ float tf32r(float x){
    uint32_t r; asm("cvt.rna.tf32.f32 %0,%1;" : "=r"(r) : "f"(x));
    return __uint_as_float(r);
}
__device__ __forceinline__ void mma16n8k8(
    float& d0, float& d1, float& d2, float& d3,
    uint32_t a0, uint32_t a1, uint32_t a2, uint32_t a3,
    uint32_t b0, uint32_t b1,
    float c0, float c1, float c2, float c3)
{
    asm volatile(
        "mma.sync.aligned.m16n8k8.row.col.f32.tf32.tf32.f32 "
        "{%0,%1,%2,%3},{%4,%5,%6,%7},{%8,%9},{%10,%11,%12,%13};"
        : "=f"(d0),"=f"(d1),"=f"(d2),"=f"(d3)
        : "r"(a0),"r"(a1),"r"(a2),"r"(a3),"r"(b0),"r"(b1),
          "f"(c0),"f"(c1),"f"(c2),"f"(c3));
}

__global__ __launch_bounds__(768, 1)
void attn_aug2d_mma(const float* __restrict__ inp,
                    const float* __restrict__ relw,
                    const float* __restrict__ relh,
                    float* __restrict__ out)
{
    extern __shared__ float sm[];
    const int tid  = threadIdx.x;
    const int warp = tid >> 5;
    const int lane = tid & 31;
    const int g    = lane >> 2;        // fragment row group
    const int t    = lane & 3;         // thread-in-group
    const int strip = warp >> 3;       // 0..2 : 48-key strip within 144-tile
    const int mrow  = (warp & 7) << 4; // 16-query row block
    const int h = blockIdx.y, b = blockIdx.z;
    const int qbase = blockIdx.x * QTQ;

    // ---- stage K,V transposed for whole (b,h): KT[d][key], VT[d][key] ----
    for (int idx = tid; idx < Nn*2; idx += 768){
        int key = idx >> 1, seg = idx & 1;
        const float* p = inp + ((size_t)(b*Nn + key))*Cc + h*8 + seg*4;
        float4 kv = *(const float4*)(p + 64);
        float4 vv = *(const float4*)(p + 128);
        int d = seg*4;
        sm[W_KT + (d+0)*KROW + key] = tf32r(kv.x);
        sm[W_KT + (d+1)*KROW + key] = tf32r(kv.y);
        sm[W_KT + (d+2)*KROW + key] = tf32r(kv.z);
        sm[W_KT + (d+3)*KROW + key] = tf32r(kv.w);
        sm[W_VT + (d+0)*KROW + key] = tf32r(vv.x);
        sm[W_VT + (d+1)*KROW + key] = tf32r(vv.y);
        sm[W_VT + (d+2)*KROW + key] = tf32r(vv.z);
        sm[W_VT + (d+3)*KROW + key] = tf32r(vv.w);
    }

    // ---- bias tables: phT[q][X] (stride 49), pwT[q][Y] (stride 50) ----
    for (int e = tid; e < 2*128*48; e += 768){
        int t0  = (e >= 6144);
        int rem = e - t0*6144;
        int q   = rem / 48;
        int pos = rem - q*48;
        int n   = qbase + q;
        int x   = n / 48, y = n - x*48;
        const float* qp  = inp + ((size_t)(b*Nn + n))*Cc + h*8;
        const float* rel = t0 ? (relw + (pos - y + 47)*8) : (relh + (pos - x + 47)*8);
        float s = 0.f;
        #pragma unroll
        for (int d = 0; d < 8; d++) s += qp[d]*rel[d];
        sm[(t0 ? (W_PW + q*50) : (W_PH + q*49)) + pos] = s * SL2E;
    }

    // ---- Q fragment (A of GEMM1), tf32-rounded, pre-scaled ----
    const int qa = mrow + g, qb = qa + 8;
    const float* qpa = inp + ((size_t)(b*Nn + qbase + qa))*Cc + h*8;
    const float* qpb = inp + ((size_t)(b*Nn + qbase + qb))*Cc + h*8;
    const uint32_t aq0 = __float_as_uint(tf32r(qpa[t]   * SL2E));
    const uint32_t aq1 = __float_as_uint(tf32r(qpb[t]   * SL2E));
    const uint32_t aq2 = __float_as_uint(tf32r(qpa[t+4] * SL2E));
    const uint32_t aq3 = __float_as_uint(tf32r(qpb[t+4] * SL2E));

    __syncthreads();

    float o0=0.f, o1=0.f, o2=0.f, o3=0.f;
    float sum0=0.f, sum1=0.f;
    const int idx0 = (lane & ~3) | (t >> 1);
    const int idx1 = idx0 + 2;
    const bool hi  = (t & 1);

    for (int tile = 0; tile < NTILES; tile++){
        const int X   = 3*tile + strip;
        const int kst = tile*KTILE + strip*48;
        const float pha = sm[W_PH + qa*49 + X];
        const float phb = sm[W_PH + qb*49 + X];

        #pragma unroll
        for (int j = 0; j < 6; j++){
            const int kj = kst + 8*j;
            uint32_t kb0 = __float_as_uint(sm[W_KT + t*KROW     + kj + g]);
            uint32_t kb1 = __float_as_uint(sm[W_KT + (t+4)*KROW + kj + g]);
            float s0, s1, s2, s3;
            mma16n8k8(s0,s1,s2,s3, aq0,aq1,aq2,aq3, kb0,kb1, 0.f,0.f,0.f,0.f);

            float2 pwa = *(const float2*)&sm[W_PW + qa*50 + 8*j + 2*t];
            float2 pwb = *(const float2*)&sm[W_PW + qb*50 + 8*j + 2*t];
            float w0f = tf32r(ex2f(s0 + pha + pwa.x));
            float w1f = tf32r(ex2f(s1 + pha + pwa.y));
            float w2f = tf32r(ex2f(s2 + phb + pwb.x));
            float w3f = tf32r(ex2f(s3 + phb + pwb.y));
            sum0 += w0f + w1f;
            sum1 += w2f + w3f;

            uint32_t w0 = __float_as_uint(w0f), w1 = __float_as_uint(w1f);
            uint32_t w2 = __float_as_uint(w2f), w3 = __float_as_uint(w3f);
            uint32_t u0, u1;
            u0 = __shfl_sync(0xffffffffu, w0, idx0);
            u1 = __shfl_sync(0xffffffffu, w1, idx0);
            uint32_t a0 = hi ? u1 : u0;
            u0 = __shfl_sync(0xffffffffu, w0, idx1);
            u1 = __shfl_sync(0xffffffffu, w1, idx1);
            uint32_t a2 = hi ? u1 : u0;
            u0 = __shfl_sync(0xffffffffu, w2, idx0);
            u1 = __shfl_sync(0xffffffffu, w3, idx0);
            uint32_t a1 = hi ? u1 : u0;
            u0 = __shfl_sync(0xffffffffu, w2, idx1);
            u1 = __shfl_sync(0xffffffffu, w3, idx1);
            uint32_t a3 = hi ? u1 : u0;

            uint32_t vb0 = __float_as_uint(sm[W_VT + g*KROW + kj + t]);
            uint32_t vb1 = __float_as_uint(sm[W_VT + g*KROW + kj + t + 4]);
            mma16n8k8(o0,o1,o2,o3, a0,a1,a2,a3, vb0,vb1, o0,o1,o2,o3);
        }
    }

    // ---- reduce sums within t-group ----
    sum0 += __shfl_xor_sync(0xffffffffu, sum0, 1);
    sum0 += __shfl_xor_sync(0xffffffffu, sum0, 2);
    sum1 += __shfl_xor_sync(0xffffffffu, sum1, 1);
    sum1 += __shfl_xor_sync(0xffffffffu, sum1, 2);
    if (t == 0){
        sm[W_SS + strip*128 + qa] = sum0;
        sm[W_SS + strip*128 + qb] = sum1;
    }
    *(float2*)&sm[W_OS + strip*1024 + qa*8 + 2*t] = make_float2(o0, o1);
    *(float2*)&sm[W_OS + strip*1024 + qb*8 + 2*t] = make_float2(o2, o3);
    __syncthreads();

    // ---- combine strips, normalize, write ----
    if (tid < 128){
        int q = tid;
        float r = 1.0f / (sm[W_SS + q] + sm[W_SS + 128 + q] + sm[W_SS + 256 + q]);
        float* op = out + ((size_t)(b*Nn + qbase + q))*64 + h*8;
        #pragma unroll
        for (int half = 0; half < 2; half++){
            float4 A = *(float4*)&sm[W_OS +        q*8 + half*4];
            float4 B = *(float4*)&sm[W_OS + 1024 + q*8 + half*4];
            float4 C = *(float4*)&sm[W_OS + 2048 + q*8 + half*4];
            ((float4*)op)[half] = make_float4((A.x+B.x+C.x)*r, (A.y+B.y+C.y)*r,
                                              (A.z+B.z+C.z)*r, (A.w+B.w+C.w)*r);
        }
    }
}

extern "C" void kernel_launch(void* const* d_in, const int* in_sizes, int n_in,
                              void* d_out, int out_size)
{
    const float* inp  = (const float*)d_in[0];
    const float* relw = (const float*)d_in[1];
    const float* relh = (const float*)d_in[2];
    float* out = (float*)d_out;

    cudaFuncSetAttribute(attn_aug2d_mma,
                         cudaFuncAttributeMaxDynamicSharedMemorySize, SMEM_BYTES);
    dim3 grid(Nn/QTQ, 8, 2);
    attn_aug2d_mma<<<grid, 768, SMEM_BYTES>>>(inp, relw, relh, out);
}

// round 10
// speedup vs baseline: 1.8986x; 1.3242x over previous
#include <cuda_runtime.h>
#include <cuda_fp16.h>
#include <cstdint>

#define Nn 2304
#define Cc 192
#define QTQ 128        // queries per CTA
#define KTILE 144      // keys per tile (3 X-rows)
#define NTILES 16
#define KROW 2312      // KT row stride (2312 % 32 == 8 -> conflict-free k-frags)
#define VROW 1156      // VH row stride in u32 (1156 % 32 == 4 -> conflict-free)
#define SL2E 0.5100420914154871f

// smem float offsets
#define W_KT   0                       // KT f32 [8][KROW]
#define W_VH   (8*KROW)                // VH u32 [8][VROW]  (f16x2 key pairs)
#define W_PH   (W_VH + 8*VROW)         // phT[128][49]
#define W_PW   (W_PH + 128*49)         // pwT[128][50]
#define W_OS   (W_PW + 128*50)         // O partials [3][128][8]
#define W_SS   (W_OS + 3*128*8)        // sums [3][128]
#define SMEM_BYTES ((W_SS + 3*128)*4)

__device__ __forceinline__ float ex2f(float x){
    float r; asm("ex2.approx.f32 %0,%1;" : "=f"(r) : "f"(x)); return r;
}
__device__ __forceinline__ float tf32r(float x){
    uint32_t r; asm("cvt.rna.tf32.f32 %0,%1;" : "=r"(r) : "f"(x));
    return __uint_as_float(r);
}
__device__ __forceinline__ uint32_t pkh2(float lo, float hi){
    __half2 h = __floats2half2_rn(lo, hi);   // .x = lo
    return *(uint32_t*)&h;
}
__device__ __forceinline__ void mma_tf32(
    float& d0, float& d1, float& d2, float& d3,
    uint32_t a0, uint32_t a1, uint32_t a2, uint32_t a3,
    uint32_t b0, uint32_t b1)
{
    asm volatile(
        "mma.sync.aligned.m16n8k8.row.col.f32.tf32.tf32.f32 "
        "{%0,%1,%2,%3},{%4,%5,%6,%7},{%8,%9},{%10,%11,%12,%13};"
        : "=f"(d0),"=f"(d1),"=f"(d2),"=f"(d3)
        : "r"(a0),"r"(a1),"r"(a2),"r"(a3),"r"(b0),"r"(b1),
          "f"(0.f),"f"(0.f),"f"(0.f),"f"(0.f));
}
__device__ __forceinline__ void mma_f16(
    float& d0, float& d1, float& d2, float& d3,
    uint32_t a0, uint32_t a1, uint32_t a2, uint32_t a3,
    uint32_t b0, uint32_t b1,
    float c0, float c1, float c2, float c3)
{
    asm volatile(
        "mma.sync.aligned.m16n8k16.row.col.f32.f16.f16.f32 "
        "{%0,%1,%2,%3},{%4,%5,%6,%7},{%8,%9},{%10,%11,%12,%13};"
        : "=f"(d0),"=f"(d1),"=f"(d2),"=f"(d3)
        : "r"(a0),"r"(a1),"r"(a2),"r"(a3),"r"(b0),"r"(b1),
          "f"(c0),"f"(c1),"f"(c2),"f"(c3));
}

__global__ __launch_bounds__(768, 1)
void attn_aug2d_mma(const float* __restrict__ inp,
                    const float* __restrict__ relw,
                    const float* __restrict__ relh,
                    float* __restrict__ out)
{
    extern __shared__ float sm[];
    uint32_t* smu = (uint32_t*)sm;
    const int tid  = threadIdx.x;
    const int warp = tid >> 5;
    const int lane = tid & 31;
    const int g    = lane >> 2;
    const int t    = lane & 3;
    const int strip = warp >> 3;        // 0..2
    const int mrow  = (warp & 7) << 4;
    const int h = blockIdx.y, b = blockIdx.z;
    const int qbase = blockIdx.x * QTQ;

    // ---- stage K transposed (tf32): KT[d][key] ----
    for (int key = tid; key < Nn; key += 768){
        const float* p = inp + ((size_t)(b*Nn + key))*Cc + h*8 + 64;
        float4 k0 = *(const float4*)(p);
        float4 k1 = *(const float4*)(p + 4);
        sm[W_KT + 0*KROW + key] = tf32r(k0.x);
        sm[W_KT + 1*KROW + key] = tf32r(k0.y);
        sm[W_KT + 2*KROW + key] = tf32r(k0.z);
        sm[W_KT + 3*KROW + key] = tf32r(k0.w);
        sm[W_KT + 4*KROW + key] = tf32r(k1.x);
        sm[W_KT + 5*KROW + key] = tf32r(k1.y);
        sm[W_KT + 6*KROW + key] = tf32r(k1.z);
        sm[W_KT + 7*KROW + key] = tf32r(k1.w);
    }
    // ---- stage V as f16x2 key-pairs: VH[d][pair] ----
    for (int pr = tid; pr < Nn/2; pr += 768){
        const float* p0 = inp + ((size_t)(b*Nn + 2*pr))*Cc + h*8 + 128;
        const float* p1 = p0 + Cc;
        float4 a0 = *(const float4*)(p0), a1 = *(const float4*)(p0 + 4);
        float4 c0 = *(const float4*)(p1), c1 = *(const float4*)(p1 + 4);
        smu[W_VH + 0*VROW + pr] = pkh2(a0.x, c0.x);
        smu[W_VH + 1*VROW + pr] = pkh2(a0.y, c0.y);
        smu[W_VH + 2*VROW + pr] = pkh2(a0.z, c0.z);
        smu[W_VH + 3*VROW + pr] = pkh2(a0.w, c0.w);
        smu[W_VH + 4*VROW + pr] = pkh2(a1.x, c1.x);
        smu[W_VH + 5*VROW + pr] = pkh2(a1.y, c1.y);
        smu[W_VH + 6*VROW + pr] = pkh2(a1.z, c1.z);
        smu[W_VH + 7*VROW + pr] = pkh2(a1.w, c1.w);
    }

    // ---- bias tables: phT[q][X] (stride 49), pwT[q][Y] (stride 50) ----
    for (int e = tid; e < 2*128*48; e += 768){
        int t0  = (e >= 6144);
        int rem = e - t0*6144;
        int q   = rem / 48;
        int pos = rem - q*48;
        int n   = qbase + q;
        int x   = n / 48, y = n - x*48;
        const float* qp  = inp + ((size_t)(b*Nn + n))*Cc + h*8;
        const float* rel = t0 ? (relw + (pos - y + 47)*8) : (relh + (pos - x + 47)*8);
        float s = 0.f;
        #pragma unroll
        for (int d = 0; d < 8; d++) s += qp[d]*rel[d];
        sm[(t0 ? (W_PW + q*50) : (W_PH + q*49)) + pos] = s * SL2E;
    }

    // ---- Q fragment (GEMM1 A), tf32, pre-scaled ----
    const int qa = mrow + g, qb = qa + 8;
    const float* qpa = inp + ((size_t)(b*Nn + qbase + qa))*Cc + h*8;
    const float* qpb = inp + ((size_t)(b*Nn + qbase + qb))*Cc + h*8;
    const uint32_t aq0 = __float_as_uint(tf32r(qpa[t]   * SL2E));
    const uint32_t aq1 = __float_as_uint(tf32r(qpb[t]   * SL2E));
    const uint32_t aq2 = __float_as_uint(tf32r(qpa[t+4] * SL2E));
    const uint32_t aq3 = __float_as_uint(tf32r(qpb[t+4] * SL2E));

    __syncthreads();

    float o0=0.f, o1=0.f, o2=0.f, o3=0.f;
    float sum0=0.f, sum1=0.f;

    for (int tile = 0; tile < NTILES; tile++){
        const int X   = 3*tile + strip;
        const int K0t = tile*KTILE + strip*48;
        const float pha = sm[W_PH + qa*49 + X];
        const float phb = sm[W_PH + qb*49 + X];

        #pragma unroll
        for (int jj = 0; jj < 3; jj++){
            const int K0 = K0t + 16*jj;
            // GEMM1 x2 (keys K0..K0+7, K0+8..K0+15)
            uint32_t kb0l = __float_as_uint(sm[W_KT + t*KROW     + K0 + g]);
            uint32_t kb1l = __float_as_uint(sm[W_KT + (t+4)*KROW + K0 + g]);
            uint32_t kb0h = __float_as_uint(sm[W_KT + t*KROW     + K0 + 8 + g]);
            uint32_t kb1h = __float_as_uint(sm[W_KT + (t+4)*KROW + K0 + 8 + g]);
            float l0,l1,l2,l3, h0,h1,h2,h3;
            mma_tf32(l0,l1,l2,l3, aq0,aq1,aq2,aq3, kb0l,kb1l);
            mma_tf32(h0,h1,h2,h3, aq0,aq1,aq2,aq3, kb0h,kb1h);

            // bias + exp; Y (strip-local) = 16*jj + {2t,2t+1} / +8
            const int Y = 16*jj + 2*t;
            float2 pal = *(const float2*)&sm[W_PW + qa*50 + Y];
            float2 pbl = *(const float2*)&sm[W_PW + qb*50 + Y];
            float2 pah = *(const float2*)&sm[W_PW + qa*50 + Y + 8];
            float2 pbh = *(const float2*)&sm[W_PW + qb*50 + Y + 8];
            float wl0 = ex2f(l0 + pha + pal.x);
            float wl1 = ex2f(l1 + pha + pal.y);
            float wl2 = ex2f(l2 + phb + pbl.x);
            float wl3 = ex2f(l3 + phb + pbl.y);
            float wh0 = ex2f(h0 + pha + pah.x);
            float wh1 = ex2f(h1 + pha + pah.y);
            float wh2 = ex2f(h2 + phb + pbh.x);
            float wh3 = ex2f(h3 + phb + pbh.y);
            sum0 += (wl0 + wl1) + (wh0 + wh1);
            sum1 += (wl2 + wl3) + (wh2 + wh3);

            // C-frags -> f16 A-frag of m16n8k16 (exact layout match, no shuffles)
            uint32_t a0 = pkh2(wl0, wl1);
            uint32_t a1 = pkh2(wl2, wl3);
            uint32_t a2 = pkh2(wh0, wh1);
            uint32_t a3 = pkh2(wh2, wh3);

            // GEMM2 B: V f16x2 pairs
            const int P0 = K0 >> 1;
            uint32_t b0 = smu[W_VH + g*VROW + P0 + t];
            uint32_t b1 = smu[W_VH + g*VROW + P0 + 4 + t];
            mma_f16(o0,o1,o2,o3, a0,a1,a2,a3, b0,b1, o0,o1,o2,o3);
        }
    }

    // ---- reduce sums within t-group ----
    sum0 += __shfl_xor_sync(0xffffffffu, sum0, 1);
    sum0 += __shfl_xor_sync(0xffffffffu, sum0, 2);
    sum1 += __shfl_xor_sync(0xffffffffu, sum1, 1);
    sum1 += __shfl_xor_sync(0xffffffffu, sum1, 2);
    if (t == 0){
        sm[W_SS + strip*128 + qa] = sum0;
        sm[W_SS + strip*128 + qb] = sum1;
    }
    *(float2*)&sm[W_OS + strip*1024 + qa*8 + 2*t] = make_float2(o0, o1);
    *(float2*)&sm[W_OS + strip*1024 + qb*8 + 2*t] = make_float2(o2, o3);
    __syncthreads();

    // ---- combine strips, normalize, write ----
    if (tid < 128){
        int q = tid;
        float r = 1.0f / (sm[W_SS + q] + sm[W_SS + 128 + q] + sm[W_SS + 256 + q]);
        float* op = out + ((size_t)(b*Nn + qbase + q))*64 + h*8;
        #pragma unroll
        for (int half = 0; half < 2; half++){
            float4 A = *(float4*)&sm[W_OS +        q*8 + half*4];
            float4 B = *(float4*)&sm[W_OS + 1024 + q*8 + half*4];
            float4 C = *(float4*)&sm[W_OS + 2048 + q*8 + half*4];
            ((float4*)op)[half] = make_float4((A.x+B.x+C.x)*r, (A.y+B.y+C.y)*r,
                                              (A.z+B.z+C.z)*r, (A.w+B.w+C.w)*r);
        }
    }
}

extern "C" void kernel_launch(void* const* d_in, const int* in_sizes, int n_in,
                              void* d_out, int out_size)
{
    const float* inp  = (const float*)d_in[0];
    const float* relw = (const float*)d_in[1];
    const float* relh = (const float*)d_in[2];
    float* out = (float*)d_out;

    cudaFuncSetAttribute(attn_aug2d_mma,
                         cudaFuncAttributeMaxDynamicSharedMemorySize, SMEM_BYTES);
    dim3 grid(Nn/QTQ, 8, 2);
    attn_aug2d_mma<<<grid, 768, SMEM_BYTES>>>(inp, relw, relh, out);
}

// round 12
// speedup vs baseline: 2.0177x; 1.0627x over previous
#include <cuda_runtime.h>
#include <cuda_fp16.h>
#include <cstdint>

#define Nn 2304
#define Cc 192
#define QTQ 128        // queries per CTA
#define KTILE 144      // keys per tile (3 X-rows)
#define NTILES 16
#define KROW2 2308     // KT2 row stride in float2 (>=2304, ==4 mod 16: conflict-free)
#define VROW2 580      // V2 row stride in uint2  (==4 mod 16: conflict-free)
#define SL2E 0.5100420914154871f

// smem float-word offsets
#define W_KT2  0                       // float2 [4][KROW2]  (k_d, k_{d+4}) per key
#define W_V2   (4*KROW2*2)             // uint2  [8][VROW2]  ((pair p),(pair p+4))
#define W_PH   (W_V2 + 8*VROW2*2)      // phT[128][49]
#define W_PW   (W_PH + 128*49)         // pwT[128][50]
#define W_OS   (W_PW + 128*50)         // O partials [3][128][8]
#define W_SS   (W_OS + 3*128*8)        // sums [3][128]
#define SMEM_BYTES ((W_SS + 3*128)*4)

__device__ __forceinline__ float ex2f(float x){
    float r; asm("ex2.approx.f32 %0,%1;" : "=f"(r) : "f"(x)); return r;
}
__device__ __forceinline__ float tf32r(float x){
    uint32_t r; asm("cvt.rna.tf32.f32 %0,%1;" : "=r"(r) : "f"(x));
    return __uint_as_float(r);
}
__device__ __forceinline__ uint32_t pkh2(float lo, float hi){
    __half2 h = __floats2half2_rn(lo, hi);
    return *(uint32_t*)&h;
}
__device__ __forceinline__ void mma_tf32(
    float& d0, float& d1, float& d2, float& d3,
    uint32_t a0, uint32_t a1, uint32_t a2, uint32_t a3,
    uint32_t b0, uint32_t b1)
{
    asm volatile(
        "mma.sync.aligned.m16n8k8.row.col.f32.tf32.tf32.f32 "
        "{%0,%1,%2,%3},{%4,%5,%6,%7},{%8,%9},{%10,%11,%12,%13};"
        : "=f"(d0),"=f"(d1),"=f"(d2),"=f"(d3)
        : "r"(a0),"r"(a1),"r"(a2),"r"(a3),"r"(b0),"r"(b1),
          "f"(0.f),"f"(0.f),"f"(0.f),"f"(0.f));
}
__device__ __forceinline__ void mma_f16(
    float& d0, float& d1, float& d2, float& d3,
    uint32_t a0, uint32_t a1, uint32_t a2, uint32_t a3,
    uint32_t b0, uint32_t b1,
    float c0, float c1, float c2, float c3)
{
    asm volatile(
        "mma.sync.aligned.m16n8k16.row.col.f32.f16.f16.f32 "
        "{%0,%1,%2,%3},{%4,%5,%6,%7},{%8,%9},{%10,%11,%12,%13};"
        : "=f"(d0),"=f"(d1),"=f"(d2),"=f"(d3)
        : "r"(a0),"r"(a1),"r"(a2),"r"(a3),"r"(b0),"r"(b1),
          "f"(c0),"f"(c1),"f"(c2),"f"(c3));
}

__global__ __launch_bounds__(768, 1)
void attn_aug2d_mma(const float* __restrict__ inp,
                    const float* __restrict__ relw,
                    const float* __restrict__ relh,
                    float* __restrict__ out)
{
    extern __shared__ float sm[];
    float2* KT2 = (float2*)sm;
    uint2*  V2  = (uint2*)(sm + W_V2);
    const int tid  = threadIdx.x;
    const int warp = tid >> 5;
    const int lane = tid & 31;
    const int g    = lane >> 2;
    const int t    = lane & 3;
    const int strip = warp >> 3;        // 0..2
    const int mrow  = (warp & 7) << 4;
    const int h = blockIdx.y, b = blockIdx.z;
    const int qbase = blockIdx.x * QTQ;

    // ---- stage K transposed, interleaved (d, d+4) float2 per key ----
    for (int key = tid; key < Nn; key += 768){
        const float* p = inp + ((size_t)(b*Nn + key))*Cc + h*8 + 64;
        float4 k0 = *(const float4*)(p);
        float4 k1 = *(const float4*)(p + 4);
        KT2[0*KROW2 + key] = make_float2(tf32r(k0.x), tf32r(k1.x));
        KT2[1*KROW2 + key] = make_float2(tf32r(k0.y), tf32r(k1.y));
        KT2[2*KROW2 + key] = make_float2(tf32r(k0.z), tf32r(k1.z));
        KT2[3*KROW2 + key] = make_float2(tf32r(k0.w), tf32r(k1.w));
    }
    // ---- stage V as paired f16x2: entry e=(blk,t4) packs pairs (blk*8+t4, +4) ----
    for (int e = tid; e < 576; e += 768){
        int blk = e >> 2, t4 = e & 3;
        int p0 = blk*8 + t4, p1 = p0 + 4;
        const float* A0 = inp + ((size_t)(b*Nn + 2*p0))*Cc + h*8 + 128;
        const float* A1 = A0 + Cc;
        const float* B0 = inp + ((size_t)(b*Nn + 2*p1))*Cc + h*8 + 128;
        const float* B1 = B0 + Cc;
        float4 a0 = *(const float4*)A0, a0h = *(const float4*)(A0+4);
        float4 a1 = *(const float4*)A1, a1h = *(const float4*)(A1+4);
        float4 b0 = *(const float4*)B0, b0h = *(const float4*)(B0+4);
        float4 b1 = *(const float4*)B1, b1h = *(const float4*)(B1+4);
        V2[0*VROW2 + e] = make_uint2(pkh2(a0.x,a1.x),  pkh2(b0.x,b1.x));
        V2[1*VROW2 + e] = make_uint2(pkh2(a0.y,a1.y),  pkh2(b0.y,b1.y));
        V2[2*VROW2 + e] = make_uint2(pkh2(a0.z,a1.z),  pkh2(b0.z,b1.z));
        V2[3*VROW2 + e] = make_uint2(pkh2(a0.w,a1.w),  pkh2(b0.w,b1.w));
        V2[4*VROW2 + e] = make_uint2(pkh2(a0h.x,a1h.x),pkh2(b0h.x,b1h.x));
        V2[5*VROW2 + e] = make_uint2(pkh2(a0h.y,a1h.y),pkh2(b0h.y,b1h.y));
        V2[6*VROW2 + e] = make_uint2(pkh2(a0h.z,a1h.z),pkh2(b0h.z,b1h.z));
        V2[7*VROW2 + e] = make_uint2(pkh2(a0h.w,a1h.w),pkh2(b0h.w,b1h.w));
    }

    // ---- bias tables: phT[q][X] (stride 49), pwT[q][Y] (stride 50) ----
    for (int e = tid; e < 2*128*48; e += 768){
        int t0  = (e >= 6144);
        int rem = e - t0*6144;
        int q   = rem / 48;
        int pos = rem - q*48;
        int n   = qbase + q;
        int x   = n / 48, y = n - x*48;
        const float* qp  = inp + ((size_t)(b*Nn + n))*Cc + h*8;
        const float* rel = t0 ? (relw + (pos - y + 47)*8) : (relh + (pos - x + 47)*8);
        float s = 0.f;
        #pragma unroll
        for (int d = 0; d < 8; d++) s += qp[d]*rel[d];
        sm[(t0 ? (W_PW + q*50) : (W_PH + q*49)) + pos] = s * SL2E;
    }

    // ---- Q fragment (GEMM1 A), tf32, pre-scaled ----
    const int qa = mrow + g, qb = qa + 8;
    const float* qpa = inp + ((size_t)(b*Nn + qbase + qa))*Cc + h*8;
    const float* qpb = inp + ((size_t)(b*Nn + qbase + qb))*Cc + h*8;
    const uint32_t aq0 = __float_as_uint(tf32r(qpa[t]   * SL2E));
    const uint32_t aq1 = __float_as_uint(tf32r(qpb[t]   * SL2E));
    const uint32_t aq2 = __float_as_uint(tf32r(qpa[t+4] * SL2E));
    const uint32_t aq3 = __float_as_uint(tf32r(qpb[t+4] * SL2E));

    __syncthreads();

    // ---- pw bias: tile-invariant -> hoist into registers ----
    float2 pal[3], pbl[3], pah[3], pbh[3];
    #pragma unroll
    for (int jj = 0; jj < 3; jj++){
        const int Y = 16*jj + 2*t;
        pal[jj] = *(const float2*)&sm[W_PW + qa*50 + Y];
        pbl[jj] = *(const float2*)&sm[W_PW + qb*50 + Y];
        pah[jj] = *(const float2*)&sm[W_PW + qa*50 + Y + 8];
        pbh[jj] = *(const float2*)&sm[W_PW + qb*50 + Y + 8];
    }

    float o0=0.f, o1=0.f, o2=0.f, o3=0.f;
    float sum0=0.f, sum1=0.f;

    for (int tile = 0; tile < NTILES; tile++){
        const int X     = 3*tile + strip;
        const int K0t   = tile*KTILE + strip*48;
        const int Vbase = tile*36 + strip*12;
        const float pha = sm[W_PH + qa*49 + X];
        const float phb = sm[W_PH + qb*49 + X];

        #pragma unroll
        for (int jj = 0; jj < 3; jj++){
            const int K0 = K0t + 16*jj;
            // GEMM1 B-frags: one LDS.64 per key octet
            float2 kl = KT2[t*KROW2 + K0 + g];
            float2 kh = KT2[t*KROW2 + K0 + 8 + g];
            float l0,l1,l2,l3, h0,h1,h2,h3;
            mma_tf32(l0,l1,l2,l3, aq0,aq1,aq2,aq3,
                     __float_as_uint(kl.x), __float_as_uint(kl.y));
            mma_tf32(h0,h1,h2,h3, aq0,aq1,aq2,aq3,
                     __float_as_uint(kh.x), __float_as_uint(kh.y));

            float wl0 = ex2f(l0 + pha + pal[jj].x);
            float wl1 = ex2f(l1 + pha + pal[jj].y);
            float wl2 = ex2f(l2 + phb + pbl[jj].x);
            float wl3 = ex2f(l3 + phb + pbl[jj].y);
            float wh0 = ex2f(h0 + pha + pah[jj].x);
            float wh1 = ex2f(h1 + pha + pah[jj].y);
            float wh2 = ex2f(h2 + phb + pbh[jj].x);
            float wh3 = ex2f(h3 + phb + pbh[jj].y);
            sum0 += (wl0 + wl1) + (wh0 + wh1);
            sum1 += (wl2 + wl3) + (wh2 + wh3);

            // C-frags -> f16 A-frag (layout identity, no shuffles)
            uint32_t a0 = pkh2(wl0, wl1);
            uint32_t a1 = pkh2(wl2, wl3);
            uint32_t a2 = pkh2(wh0, wh1);
            uint32_t a3 = pkh2(wh2, wh3);

            // GEMM2 B-frag: one LDS.64
            uint2 vv = V2[g*VROW2 + Vbase + 4*jj + t];
            mma_f16(o0,o1,o2,o3, a0,a1,a2,a3, vv.x, vv.y, o0,o1,o2,o3);
        }
    }

    // ---- reduce sums within t-group ----
    sum0 += __shfl_xor_sync(0xffffffffu, sum0, 1);
    sum0 += __shfl_xor_sync(0xffffffffu, sum0, 2);
    sum1 += __shfl_xor_sync(0xffffffffu, sum1, 1);
    sum1 += __shfl_xor_sync(0xffffffffu, sum1, 2);
    if (t == 0){
        sm[W_SS + strip*128 + qa] = sum0;
        sm[W_SS + strip*128 + qb] = sum1;
    }
    *(float2*)&sm[W_OS + strip*1024 + qa*8 + 2*t] = make_float2(o0, o1);
    *(float2*)&sm[W_OS + strip*1024 + qb*8 + 2*t] = make_float2(o2, o3);
    __syncthreads();

    // ---- combine strips, normalize, write ----
    if (tid < 128){
        int q = tid;
        float r = 1.0f / (sm[W_SS + q] + sm[W_SS + 128 + q] + sm[W_SS + 256 + q]);
        float* op = out + ((size_t)(b*Nn + qbase + q))*64 + h*8;
        #pragma unroll
        for (int half = 0; half < 2; half++){
            float4 A = *(float4*)&sm[W_OS +        q*8 + half*4];
            float4 B = *(float4*)&sm[W_OS + 1024 + q*8 + half*4];
            float4 C = *(float4*)&sm[W_OS + 2048 + q*8 + half*4];
            ((float4*)op)[half] = make_float4((A.x+B.x+C.x)*r, (A.y+B.y+C.y)*r,
                                              (A.z+B.z+C.z)*r, (A.w+B.w+C.w)*r);
        }
    }
}

extern "C" void kernel_launch(void* const* d_in, const int* in_sizes, int n_in,
                              void* d_out, int out_size)
{
    const float* inp  = (const float*)d_in[0];
    const float* relw = (const float*)d_in[1];
    const float* relh = (const float*)d_in[2];
    float* out = (float*)d_out;

    cudaFuncSetAttribute(attn_aug2d_mma,
                         cudaFuncAttributeMaxDynamicSharedMemorySize, SMEM_BYTES);
    dim3 grid(Nn/QTQ, 8, 2);
    attn_aug2d_mma<<<grid, 768, SMEM_BYTES>>>(inp, relw, relh, out);
}